// round 1
// baseline (speedup 1.0000x reference)
#include <cuda_runtime.h>
#include <math.h>

#define NE   4096
#define EMB  64
#define NB   4
#define FCO  100

// Scratch (allocation-free rule: __device__ globals)
__device__ float g_h0[NE], g_h1[NE], g_h2[NE];
__device__ float g_src[NE], g_dst[NE];
__device__ float g_q[NE], g_q2[NE], g_ca[NE], g_cb[NE], g_w0[NE];
__device__ float g_x[NB * NE * 3];

// ---------------------------------------------------------------------------
// Kernel 1: h = emb @ W  (per-node [3]), src = h@a1, dst = h@a2
// ---------------------------------------------------------------------------
__global__ void k_prep(const float* __restrict__ emb,
                       const float* __restrict__ W,
                       const float* __restrict__ av)
{
    int row = blockIdx.x * blockDim.x + threadIdx.x;
    if (row >= NE) return;
    const float* e = emb + row * EMB;
    float h0 = 0.f, h1 = 0.f, h2 = 0.f;
#pragma unroll
    for (int k = 0; k < EMB; k++) {
        float ev = __ldg(e + k);
        h0 = fmaf(ev, __ldg(W + k * 3 + 0), h0);
        h1 = fmaf(ev, __ldg(W + k * 3 + 1), h1);
        h2 = fmaf(ev, __ldg(W + k * 3 + 2), h2);
    }
    g_h0[row] = h0; g_h1[row] = h1; g_h2[row] = h2;
    g_src[row] = h0 * __ldg(av + 0) + h1 * __ldg(av + 1) + h2 * __ldg(av + 2);
    g_dst[row] = h0 * __ldg(av + 3) + h1 * __ldg(av + 4) + h2 * __ldg(av + 5);
}

// ---------------------------------------------------------------------------
// Kernel 2: Md = max(dst); per-j tables q,q2; per-i tables a,b,w0
//   C_i = max(lrelu(src_i + Md), 9e-15)  -- >= true masked row max
//   edge weight(i,j) = max(a_i*q_j, b_i*q2_j)  (exact lrelu-softmax factoring)
// ---------------------------------------------------------------------------
__global__ void k_tables()
{
    __shared__ float red[256];
    int tid = threadIdx.x;
    float m = -3.4e38f;
    for (int i = tid; i < NE; i += 256) m = fmaxf(m, g_dst[i]);
    red[tid] = m;
    __syncthreads();
    for (int s = 128; s > 0; s >>= 1) {
        if (tid < s) red[tid] = fmaxf(red[tid], red[tid + s]);
        __syncthreads();
    }
    float Md = red[0];
    for (int i = tid; i < NE; i += 256) {
        float d = g_dst[i], s = g_src[i];
        g_q[i]  = expf(d - Md);
        g_q2[i] = expf(0.2f * (d - Md));
        float z  = s + Md;
        float lr = z > 0.f ? z : 0.2f * z;
        float C  = fmaxf(lr, 9e-15f);
        g_ca[i] = expf(z - C);
        g_cb[i] = expf(0.2f * z - C);
        g_w0[i] = expf(9e-15f - C);
    }
}

// ---------------------------------------------------------------------------
// Kernel 3: fused masked-softmax * h, ELU. One warp per 4 rows.
//   Streams adj (268MB) once; per-j tables live in SMEM (80KB).
// ---------------------------------------------------------------------------
#define DO_COMP(r, AC, QC, Q2C, H0C, H1C, H2C)                               \
    {                                                                        \
        float w = (AC > 0) ? fmaxf(Ca[r] * QC, Cb[r] * Q2C) : W0[r];         \
        S[r] += w;                                                           \
        T0[r] = fmaf(w, H0C, T0[r]);                                         \
        T1[r] = fmaf(w, H1C, T1[r]);                                         \
        T2[r] = fmaf(w, H2C, T2[r]);                                         \
    }

__global__ void __launch_bounds__(256, 2) k_main(const int* __restrict__ adj)
{
    extern __shared__ float sm[];
    float* sq  = sm;
    float* sq2 = sm + NE;
    float* sh0 = sm + 2 * NE;
    float* sh1 = sm + 3 * NE;
    float* sh2 = sm + 4 * NE;
    for (int i = threadIdx.x; i < NE; i += 256) {
        sq[i] = g_q[i]; sq2[i] = g_q2[i];
        sh0[i] = g_h0[i]; sh1[i] = g_h1[i]; sh2[i] = g_h2[i];
    }
    __syncthreads();

    int warp = threadIdx.x >> 5, lane = threadIdx.x & 31;
    int g = blockIdx.x * 8 + warp;           // 4096 groups, 1 per warp
    int b = g >> 10;
    int ibase = (g & 1023) << 2;
    const int* arow = adj + ((size_t)b * NE + ibase) * NE;

    float Ca[4], Cb[4], W0[4];
#pragma unroll
    for (int r = 0; r < 4; r++) {
        Ca[r] = g_ca[ibase + r];
        Cb[r] = g_cb[ibase + r];
        W0[r] = g_w0[ibase + r];
    }
    float S[4]  = {0, 0, 0, 0}, T0[4] = {0, 0, 0, 0};
    float T1[4] = {0, 0, 0, 0}, T2[4] = {0, 0, 0, 0};

    for (int j = lane * 4; j < NE; j += 128) {
        int4 aa[4];
#pragma unroll
        for (int r = 0; r < 4; r++)
            aa[r] = *(const int4*)(arow + (size_t)r * NE + j);
        float4 Q  = *(const float4*)(sq  + j);
        float4 Q2 = *(const float4*)(sq2 + j);
        float4 H0 = *(const float4*)(sh0 + j);
        float4 H1 = *(const float4*)(sh1 + j);
        float4 H2 = *(const float4*)(sh2 + j);
#pragma unroll
        for (int r = 0; r < 4; r++) {
            DO_COMP(r, aa[r].x, Q.x, Q2.x, H0.x, H1.x, H2.x)
            DO_COMP(r, aa[r].y, Q.y, Q2.y, H0.y, H1.y, H2.y)
            DO_COMP(r, aa[r].z, Q.z, Q2.z, H0.z, H1.z, H2.z)
            DO_COMP(r, aa[r].w, Q.w, Q2.w, H0.w, H1.w, H2.w)
        }
    }

#pragma unroll
    for (int o = 16; o > 0; o >>= 1) {
#pragma unroll
        for (int r = 0; r < 4; r++) {
            S[r]  += __shfl_xor_sync(0xffffffffu, S[r],  o);
            T0[r] += __shfl_xor_sync(0xffffffffu, T0[r], o);
            T1[r] += __shfl_xor_sync(0xffffffffu, T1[r], o);
            T2[r] += __shfl_xor_sync(0xffffffffu, T2[r], o);
        }
    }
    if (lane < 4) {
        int r = lane;
        float inv = 1.f / S[r];
        float v0 = T0[r] * inv, v1 = T1[r] * inv, v2 = T2[r] * inv;
        v0 = v0 > 0.f ? v0 : expm1f(v0);
        v1 = v1 > 0.f ? v1 : expm1f(v1);
        v2 = v2 > 0.f ? v2 : expm1f(v2);
        float* xp = g_x + ((size_t)b * NE + (ibase + r)) * 3;
        xp[0] = v0; xp[1] = v1; xp[2] = v2;
    }
}

// ---------------------------------------------------------------------------
// Kernel 4: out[b,k] = sum_n x[b,n] * fc1_w[k,n] + fc1_b[k]
// ---------------------------------------------------------------------------
__global__ void __launch_bounds__(256) k_fc(const float* __restrict__ w,
                                            const float* __restrict__ bias,
                                            float* __restrict__ out)
{
    int k = blockIdx.x;
    const float* wr = w + (size_t)k * (NE * 3);
    float a0 = 0.f, a1 = 0.f, a2 = 0.f, a3 = 0.f;
    for (int n = threadIdx.x * 4; n < NE * 3; n += 256 * 4) {
        float4 wv = *(const float4*)(wr + n);
        float4 x0 = *(const float4*)(g_x + 0 * NE * 3 + n);
        float4 x1 = *(const float4*)(g_x + 1 * NE * 3 + n);
        float4 x2 = *(const float4*)(g_x + 2 * NE * 3 + n);
        float4 x3 = *(const float4*)(g_x + 3 * NE * 3 + n);
        a0 = fmaf(wv.x, x0.x, fmaf(wv.y, x0.y, fmaf(wv.z, x0.z, fmaf(wv.w, x0.w, a0))));
        a1 = fmaf(wv.x, x1.x, fmaf(wv.y, x1.y, fmaf(wv.z, x1.z, fmaf(wv.w, x1.w, a1))));
        a2 = fmaf(wv.x, x2.x, fmaf(wv.y, x2.y, fmaf(wv.z, x2.z, fmaf(wv.w, x2.w, a2))));
        a3 = fmaf(wv.x, x3.x, fmaf(wv.y, x3.y, fmaf(wv.z, x3.z, fmaf(wv.w, x3.w, a3))));
    }
#pragma unroll
    for (int o = 16; o > 0; o >>= 1) {
        a0 += __shfl_xor_sync(0xffffffffu, a0, o);
        a1 += __shfl_xor_sync(0xffffffffu, a1, o);
        a2 += __shfl_xor_sync(0xffffffffu, a2, o);
        a3 += __shfl_xor_sync(0xffffffffu, a3, o);
    }
    __shared__ float sred[4][8];
    int warp = threadIdx.x >> 5, lane = threadIdx.x & 31;
    if (lane == 0) {
        sred[0][warp] = a0; sred[1][warp] = a1;
        sred[2][warp] = a2; sred[3][warp] = a3;
    }
    __syncthreads();
    if (threadIdx.x < 4) {
        float s = 0.f;
#pragma unroll
        for (int ww = 0; ww < 8; ww++) s += sred[threadIdx.x][ww];
        out[threadIdx.x * FCO + k] = s + __ldg(bias + k);
    }
}

// ---------------------------------------------------------------------------
extern "C" void kernel_launch(void* const* d_in, const int* in_sizes, int n_in,
                              void* d_out, int out_size)
{
    const int*   adj = (const int*)d_in[0];
    const float* emb = (const float*)d_in[1];
    const float* W   = (const float*)d_in[2];
    const float* av  = (const float*)d_in[3];
    const float* fcw = (const float*)d_in[4];
    const float* fcb = (const float*)d_in[5];
    float* out = (float*)d_out;

    cudaFuncSetAttribute(k_main, cudaFuncAttributeMaxDynamicSharedMemorySize,
                         5 * NE * (int)sizeof(float));

    k_prep<<<NE / 128, 128>>>(emb, W, av);
    k_tables<<<1, 256>>>();
    k_main<<<512, 256, 5 * NE * sizeof(float)>>>(adj);
    k_fc<<<FCO, 256>>>(fcw, fcb, out);
}

// round 2
// speedup vs baseline: 1.1117x; 1.1117x over previous
#include <cuda_runtime.h>
#include <math.h>

#define NE   4096
#define EMB  64
#define NB   4
#define FCO  100

// Scratch (allocation-free rule: __device__ globals)
__device__ float g_h0[NE], g_h1[NE], g_h2[NE];
__device__ float g_src[NE], g_dst[NE];
__device__ float g_q[NE], g_q2[NE], g_ca[NE], g_cb[NE], g_w0[NE];
__device__ float g_x[NB * NE * 3];
__device__ float g_part[16 * FCO];   // [chunk(4) x batch(4) x 100]

// Packed f32x2 helpers (sm_103a)
__device__ __forceinline__ unsigned long long pack2(float lo, float hi) {
    unsigned long long r;
    asm("mov.b64 %0, {%1, %2};" : "=l"(r) : "f"(lo), "f"(hi));
    return r;
}
__device__ __forceinline__ void unpack2(float& lo, float& hi, unsigned long long v) {
    asm("mov.b64 {%0, %1}, %2;" : "=f"(lo), "=f"(hi) : "l"(v));
}
#define FMA_X2(d, a, b, c) \
    asm("fma.rn.f32x2 %0, %1, %2, %3;" : "=l"(d) : "l"(a), "l"(b), "l"(c))
#define ADD_X2(d, a, b) \
    asm("add.rn.f32x2 %0, %1, %2;" : "=l"(d) : "l"(a), "l"(b))

// ---------------------------------------------------------------------------
// Kernel 1: h = emb @ W  (per-node [3]), src = h@a1, dst = h@a2
// ---------------------------------------------------------------------------
__global__ void k_prep(const float* __restrict__ emb,
                       const float* __restrict__ W,
                       const float* __restrict__ av)
{
    int row = blockIdx.x * blockDim.x + threadIdx.x;
    if (row >= NE) return;
    const float* e = emb + row * EMB;
    float h0 = 0.f, h1 = 0.f, h2 = 0.f;
#pragma unroll
    for (int k = 0; k < EMB; k++) {
        float ev = __ldg(e + k);
        h0 = fmaf(ev, __ldg(W + k * 3 + 0), h0);
        h1 = fmaf(ev, __ldg(W + k * 3 + 1), h1);
        h2 = fmaf(ev, __ldg(W + k * 3 + 2), h2);
    }
    g_h0[row] = h0; g_h1[row] = h1; g_h2[row] = h2;
    g_src[row] = h0 * __ldg(av + 0) + h1 * __ldg(av + 1) + h2 * __ldg(av + 2);
    g_dst[row] = h0 * __ldg(av + 3) + h1 * __ldg(av + 4) + h2 * __ldg(av + 5);
}

// ---------------------------------------------------------------------------
// Kernel 2: Md = max(dst); per-j tables q,q2; per-i tables ca,cb,w0
// ---------------------------------------------------------------------------
__global__ void k_tables()
{
    __shared__ float red[256];
    int tid = threadIdx.x;
    float m = -3.4e38f;
    for (int i = tid; i < NE; i += 256) m = fmaxf(m, g_dst[i]);
    red[tid] = m;
    __syncthreads();
    for (int s = 128; s > 0; s >>= 1) {
        if (tid < s) red[tid] = fmaxf(red[tid], red[tid + s]);
        __syncthreads();
    }
    float Md = red[0];
    for (int i = tid; i < NE; i += 256) {
        float d = g_dst[i], s = g_src[i];
        g_q[i]  = expf(d - Md);
        g_q2[i] = expf(0.2f * (d - Md));
        float z  = s + Md;
        float lr = z > 0.f ? z : 0.2f * z;
        float C  = fmaxf(lr, 9e-15f);
        g_ca[i] = expf(z - C);
        g_cb[i] = expf(0.2f * z - C);
        g_w0[i] = expf(9e-15f - C);
    }
}

// ---------------------------------------------------------------------------
// Kernel 3: fused masked-softmax * h, ELU. One warp per 4 rows.
//   Software-pipelined adj stream (268MB once) + packed f32x2 accumulation.
// ---------------------------------------------------------------------------
__global__ void __launch_bounds__(256, 2) k_main(const int* __restrict__ adj)
{
    extern __shared__ float sm[];
    float* sq  = sm;
    float* sq2 = sm + NE;
    float* sh0 = sm + 2 * NE;
    float* sh1 = sm + 3 * NE;
    float* sh2 = sm + 4 * NE;
    for (int i = threadIdx.x; i < NE; i += 256) {
        sq[i] = g_q[i]; sq2[i] = g_q2[i];
        sh0[i] = g_h0[i]; sh1[i] = g_h1[i]; sh2[i] = g_h2[i];
    }
    __syncthreads();

    int warp = threadIdx.x >> 5, lane = threadIdx.x & 31;
    int g = blockIdx.x * 8 + warp;           // 4096 groups, 1 per warp
    int b = g >> 10;
    int ibase = (g & 1023) << 2;
    const int* arow = adj + ((size_t)b * NE + ibase) * NE + lane * 4;

    float Ca[4], Cb[4], W0[4];
#pragma unroll
    for (int r = 0; r < 4; r++) {
        Ca[r] = g_ca[ibase + r];
        Cb[r] = g_cb[ibase + r];
        W0[r] = g_w0[ibase + r];
    }
    unsigned long long Sp[4], T0p[4], T1p[4], T2p[4];
#pragma unroll
    for (int r = 0; r < 4; r++) { Sp[r] = 0ull; T0p[r] = 0ull; T1p[r] = 0ull; T2p[r] = 0ull; }

    const int ITERS = NE / 128;              // 32
    int4 aa[4];
#pragma unroll
    for (int r = 0; r < 4; r++)
        aa[r] = __ldcs((const int4*)(arow + (size_t)r * NE));

    for (int k = 0; k < ITERS; k++) {
        int j = lane * 4 + k * 128;
        int4 nx[4];
        if (k + 1 < ITERS) {
#pragma unroll
            for (int r = 0; r < 4; r++)
                nx[r] = __ldcs((const int4*)(arow + (size_t)r * NE + (k + 1) * 128));
        }
        float4  Q  = *(const float4*)(sq  + j);
        float4  Q2 = *(const float4*)(sq2 + j);
        double2 H0 = *(const double2*)(sh0 + j);
        double2 H1 = *(const double2*)(sh1 + j);
        double2 H2 = *(const double2*)(sh2 + j);
        unsigned long long h0lo = __double_as_longlong(H0.x), h0hi = __double_as_longlong(H0.y);
        unsigned long long h1lo = __double_as_longlong(H1.x), h1hi = __double_as_longlong(H1.y);
        unsigned long long h2lo = __double_as_longlong(H2.x), h2hi = __double_as_longlong(H2.y);

#pragma unroll
        for (int r = 0; r < 4; r++) {
            float m0 = fmaxf(Ca[r] * Q.x,  Cb[r] * Q2.x);
            float m1 = fmaxf(Ca[r] * Q.y,  Cb[r] * Q2.y);
            float m2 = fmaxf(Ca[r] * Q.z,  Cb[r] * Q2.z);
            float m3 = fmaxf(Ca[r] * Q.w,  Cb[r] * Q2.w);
            float w0 = (aa[r].x > 0) ? m0 : W0[r];
            float w1 = (aa[r].y > 0) ? m1 : W0[r];
            float w2 = (aa[r].z > 0) ? m2 : W0[r];
            float w3 = (aa[r].w > 0) ? m3 : W0[r];
            unsigned long long wlo = pack2(w0, w1);
            unsigned long long whi = pack2(w2, w3);
            ADD_X2(Sp[r], Sp[r], wlo);
            ADD_X2(Sp[r], Sp[r], whi);
            FMA_X2(T0p[r], wlo, h0lo, T0p[r]);
            FMA_X2(T0p[r], whi, h0hi, T0p[r]);
            FMA_X2(T1p[r], wlo, h1lo, T1p[r]);
            FMA_X2(T1p[r], whi, h1hi, T1p[r]);
            FMA_X2(T2p[r], wlo, h2lo, T2p[r]);
            FMA_X2(T2p[r], whi, h2hi, T2p[r]);
        }
#pragma unroll
        for (int r = 0; r < 4; r++) aa[r] = nx[r];
    }

    // fold packed lanes, then warp reduce
    float S[4], T0[4], T1[4], T2[4];
#pragma unroll
    for (int r = 0; r < 4; r++) {
        float lo, hi;
        unpack2(lo, hi, Sp[r]);  S[r]  = lo + hi;
        unpack2(lo, hi, T0p[r]); T0[r] = lo + hi;
        unpack2(lo, hi, T1p[r]); T1[r] = lo + hi;
        unpack2(lo, hi, T2p[r]); T2[r] = lo + hi;
    }
#pragma unroll
    for (int o = 16; o > 0; o >>= 1) {
#pragma unroll
        for (int r = 0; r < 4; r++) {
            S[r]  += __shfl_xor_sync(0xffffffffu, S[r],  o);
            T0[r] += __shfl_xor_sync(0xffffffffu, T0[r], o);
            T1[r] += __shfl_xor_sync(0xffffffffu, T1[r], o);
            T2[r] += __shfl_xor_sync(0xffffffffu, T2[r], o);
        }
    }
    if (lane < 4) {
        int r = lane;
        float inv = 1.f / S[r];
        float v0 = T0[r] * inv, v1 = T1[r] * inv, v2 = T2[r] * inv;
        v0 = v0 > 0.f ? v0 : expm1f(v0);
        v1 = v1 > 0.f ? v1 : expm1f(v1);
        v2 = v2 > 0.f ? v2 : expm1f(v2);
        float* xp = g_x + ((size_t)b * NE + (ibase + r)) * 3;
        xp[0] = v0; xp[1] = v1; xp[2] = v2;
    }
}

// ---------------------------------------------------------------------------
// Kernel 4a: partial FC. grid (100, 4): block (k, chunk). chunk = 3072 floats.
// ---------------------------------------------------------------------------
__global__ void __launch_bounds__(256) k_fc1(const float* __restrict__ w)
{
    int k = blockIdx.x, c = blockIdx.y;
    int n0 = c * 3072;
    const float* wr = w + (size_t)k * (NE * 3) + n0;
    const float* x0 = g_x + 0 * NE * 3 + n0;
    const float* x1 = g_x + 1 * NE * 3 + n0;
    const float* x2 = g_x + 2 * NE * 3 + n0;
    const float* x3 = g_x + 3 * NE * 3 + n0;
    float a0 = 0.f, a1 = 0.f, a2 = 0.f, a3 = 0.f;
#pragma unroll
    for (int t = 0; t < 3; t++) {
        int n = threadIdx.x * 4 + t * 1024;
        float4 wv = *(const float4*)(wr + n);
        float4 v0 = *(const float4*)(x0 + n);
        float4 v1 = *(const float4*)(x1 + n);
        float4 v2 = *(const float4*)(x2 + n);
        float4 v3 = *(const float4*)(x3 + n);
        a0 = fmaf(wv.x, v0.x, fmaf(wv.y, v0.y, fmaf(wv.z, v0.z, fmaf(wv.w, v0.w, a0))));
        a1 = fmaf(wv.x, v1.x, fmaf(wv.y, v1.y, fmaf(wv.z, v1.z, fmaf(wv.w, v1.w, a1))));
        a2 = fmaf(wv.x, v2.x, fmaf(wv.y, v2.y, fmaf(wv.z, v2.z, fmaf(wv.w, v2.w, a2))));
        a3 = fmaf(wv.x, v3.x, fmaf(wv.y, v3.y, fmaf(wv.z, v3.z, fmaf(wv.w, v3.w, a3))));
    }
#pragma unroll
    for (int o = 16; o > 0; o >>= 1) {
        a0 += __shfl_xor_sync(0xffffffffu, a0, o);
        a1 += __shfl_xor_sync(0xffffffffu, a1, o);
        a2 += __shfl_xor_sync(0xffffffffu, a2, o);
        a3 += __shfl_xor_sync(0xffffffffu, a3, o);
    }
    __shared__ float sred[4][8];
    int wrp = threadIdx.x >> 5, lane = threadIdx.x & 31;
    if (lane == 0) {
        sred[0][wrp] = a0; sred[1][wrp] = a1;
        sred[2][wrp] = a2; sred[3][wrp] = a3;
    }
    __syncthreads();
    if (threadIdx.x < 4) {
        float s = 0.f;
#pragma unroll
        for (int ww = 0; ww < 8; ww++) s += sred[threadIdx.x][ww];
        g_part[(c * 4 + threadIdx.x) * FCO + k] = s;
    }
}

// Kernel 4b: reduce partials + bias
__global__ void k_fc2(const float* __restrict__ bias, float* __restrict__ out)
{
    int tid = threadIdx.x;
    if (tid >= 4 * FCO) return;
    int b = tid / FCO, k = tid % FCO;
    float s = __ldg(bias + k);
#pragma unroll
    for (int c = 0; c < 4; c++) s += g_part[(c * 4 + b) * FCO + k];
    out[b * FCO + k] = s;
}

// ---------------------------------------------------------------------------
extern "C" void kernel_launch(void* const* d_in, const int* in_sizes, int n_in,
                              void* d_out, int out_size)
{
    const int*   adj = (const int*)d_in[0];
    const float* emb = (const float*)d_in[1];
    const float* W   = (const float*)d_in[2];
    const float* av  = (const float*)d_in[3];
    const float* fcw = (const float*)d_in[4];
    const float* fcb = (const float*)d_in[5];
    float* out = (float*)d_out;

    cudaFuncSetAttribute(k_main, cudaFuncAttributeMaxDynamicSharedMemorySize,
                         5 * NE * (int)sizeof(float));

    k_prep<<<NE / 128, 128>>>(emb, W, av);
    k_tables<<<1, 256>>>();
    k_main<<<512, 256, 5 * NE * sizeof(float)>>>(adj);
    k_fc1<<<dim3(FCO, 4), 256>>>(fcw);
    k_fc2<<<1, 512>>>(fcb, out);
}

// round 3
// speedup vs baseline: 1.1738x; 1.0558x over previous
#include <cuda_runtime.h>
#include <math.h>

#define NE   4096
#define EMB  64
#define NB   4
#define FCO  100
#define NCHUNK 12

// Scratch (allocation-free rule: __device__ globals)
__device__ float g_h0[NE], g_h1[NE], g_h2[NE];
__device__ float g_src[NE], g_dst[NE];
__device__ float g_q[NE], g_q2[NE], g_ca[NE], g_cb[NE], g_w0[NE];
__device__ float g_x[NB * NE * 3];
__device__ float g_part[NCHUNK * NB * FCO];
__device__ unsigned g_mbits;

// Order-preserving float<->uint encoding for atomicMax
__device__ __forceinline__ unsigned enc_f(float f) {
    unsigned b = __float_as_uint(f);
    return (b & 0x80000000u) ? ~b : (b | 0x80000000u);
}
__device__ __forceinline__ float dec_f(unsigned u) {
    unsigned b = (u & 0x80000000u) ? (u & 0x7fffffffu) : ~u;
    return __uint_as_float(b);
}

// Packed f32x2 helpers (sm_103a)
__device__ __forceinline__ unsigned long long pack2(float lo, float hi) {
    unsigned long long r;
    asm("mov.b64 %0, {%1, %2};" : "=l"(r) : "f"(lo), "f"(hi));
    return r;
}
__device__ __forceinline__ void unpack2(float& lo, float& hi, unsigned long long v) {
    asm("mov.b64 {%0, %1}, %2;" : "=f"(lo), "=f"(hi) : "l"(v));
}
#define FMA_X2(d, a, b, c) \
    asm("fma.rn.f32x2 %0, %1, %2, %3;" : "=l"(d) : "l"(a), "l"(b), "l"(c))
#define ADD_X2(d, a, b) \
    asm("add.rn.f32x2 %0, %1, %2;" : "=l"(d) : "l"(a), "l"(b))

// ---------------------------------------------------------------------------
__global__ void k_init() { g_mbits = 0u; }   // 0 < enc(x) for all finite x

// Kernel 1: h = emb @ W, src/dst projections, global max(dst) via atomicMax
__global__ void k_prep(const float* __restrict__ emb,
                       const float* __restrict__ W,
                       const float* __restrict__ av)
{
    int row = blockIdx.x * blockDim.x + threadIdx.x;
    if (row >= NE) return;
    const float* e = emb + row * EMB;
    float h0 = 0.f, h1 = 0.f, h2 = 0.f;
#pragma unroll
    for (int k = 0; k < EMB; k++) {
        float ev = __ldg(e + k);
        h0 = fmaf(ev, __ldg(W + k * 3 + 0), h0);
        h1 = fmaf(ev, __ldg(W + k * 3 + 1), h1);
        h2 = fmaf(ev, __ldg(W + k * 3 + 2), h2);
    }
    g_h0[row] = h0; g_h1[row] = h1; g_h2[row] = h2;
    float s = h0 * __ldg(av + 0) + h1 * __ldg(av + 1) + h2 * __ldg(av + 2);
    float d = h0 * __ldg(av + 3) + h1 * __ldg(av + 4) + h2 * __ldg(av + 5);
    g_src[row] = s;
    g_dst[row] = d;
    atomicMax(&g_mbits, enc_f(d));
}

// Kernel 2: per-j tables q,q2; per-i tables ca,cb,w0 (grid-wide now)
__global__ void k_tables()
{
    int i = blockIdx.x * blockDim.x + threadIdx.x;
    if (i >= NE) return;
    float Md = dec_f(g_mbits);
    float d = g_dst[i], s = g_src[i];
    g_q[i]  = expf(d - Md);
    g_q2[i] = expf(0.2f * (d - Md));
    float z  = s + Md;
    float lr = z > 0.f ? z : 0.2f * z;
    float C  = fmaxf(lr, 9e-15f);
    g_ca[i] = expf(z - C);
    g_cb[i] = expf(0.2f * z - C);
    g_w0[i] = expf(9e-15f - C);
}

// ---------------------------------------------------------------------------
// Kernel 3: fused masked-softmax * h, ELU. One warp per 4 rows.
//   Depth-2 prefetch: 8 LDG.128 in flight per warp -> ~64KB/SM in flight.
// ---------------------------------------------------------------------------
__global__ void __launch_bounds__(256, 2) k_main(const int* __restrict__ adj)
{
    extern __shared__ float sm[];
    float* sq  = sm;
    float* sq2 = sm + NE;
    float* sh0 = sm + 2 * NE;
    float* sh1 = sm + 3 * NE;
    float* sh2 = sm + 4 * NE;
    for (int i = threadIdx.x; i < NE; i += 256) {
        sq[i] = g_q[i]; sq2[i] = g_q2[i];
        sh0[i] = g_h0[i]; sh1[i] = g_h1[i]; sh2[i] = g_h2[i];
    }
    __syncthreads();

    int warp = threadIdx.x >> 5, lane = threadIdx.x & 31;
    int g = blockIdx.x * 8 + warp;           // 4096 groups, 1 per warp
    int b = g >> 10;
    int ibase = (g & 1023) << 2;

    const int4* arow[4];
#pragma unroll
    for (int r = 0; r < 4; r++)
        arow[r] = (const int4*)(adj + ((size_t)b * NE + ibase + r) * NE) + lane;

    float Ca[4], Cb[4], W0[4];
#pragma unroll
    for (int r = 0; r < 4; r++) {
        Ca[r] = g_ca[ibase + r];
        Cb[r] = g_cb[ibase + r];
        W0[r] = g_w0[ibase + r];
    }
    unsigned long long Sp[4], T0p[4], T1p[4], T2p[4];
#pragma unroll
    for (int r = 0; r < 4; r++) { Sp[r] = 0ull; T0p[r] = 0ull; T1p[r] = 0ull; T2p[r] = 0ull; }

    const int ITERS = NE / 128;              // 32
    int4 A[4], B[4], C[4];
#pragma unroll
    for (int r = 0; r < 4; r++) A[r] = __ldcs(arow[r]);
#pragma unroll
    for (int r = 0; r < 4; r++) B[r] = __ldcs(arow[r] + 32);

#pragma unroll 2
    for (int k = 0; k < ITERS; k++) {
        if (k + 2 < ITERS) {
#pragma unroll
            for (int r = 0; r < 4; r++)
                C[r] = __ldcs(arow[r] + (k + 2) * 32);
        }
        int j = lane * 4 + k * 128;
        float4  Q  = *(const float4*)(sq  + j);
        float4  Q2 = *(const float4*)(sq2 + j);
        double2 H0 = *(const double2*)(sh0 + j);
        double2 H1 = *(const double2*)(sh1 + j);
        double2 H2 = *(const double2*)(sh2 + j);
        unsigned long long h0lo = __double_as_longlong(H0.x), h0hi = __double_as_longlong(H0.y);
        unsigned long long h1lo = __double_as_longlong(H1.x), h1hi = __double_as_longlong(H1.y);
        unsigned long long h2lo = __double_as_longlong(H2.x), h2hi = __double_as_longlong(H2.y);

#pragma unroll
        for (int r = 0; r < 4; r++) {
            float m0 = fmaxf(Ca[r] * Q.x,  Cb[r] * Q2.x);
            float m1 = fmaxf(Ca[r] * Q.y,  Cb[r] * Q2.y);
            float m2 = fmaxf(Ca[r] * Q.z,  Cb[r] * Q2.z);
            float m3 = fmaxf(Ca[r] * Q.w,  Cb[r] * Q2.w);
            float w0 = (A[r].x > 0) ? m0 : W0[r];
            float w1 = (A[r].y > 0) ? m1 : W0[r];
            float w2 = (A[r].z > 0) ? m2 : W0[r];
            float w3 = (A[r].w > 0) ? m3 : W0[r];
            unsigned long long wlo = pack2(w0, w1);
            unsigned long long whi = pack2(w2, w3);
            ADD_X2(Sp[r], Sp[r], wlo);
            ADD_X2(Sp[r], Sp[r], whi);
            FMA_X2(T0p[r], wlo, h0lo, T0p[r]);
            FMA_X2(T0p[r], whi, h0hi, T0p[r]);
            FMA_X2(T1p[r], wlo, h1lo, T1p[r]);
            FMA_X2(T1p[r], whi, h1hi, T1p[r]);
            FMA_X2(T2p[r], wlo, h2lo, T2p[r]);
            FMA_X2(T2p[r], whi, h2hi, T2p[r]);
        }
#pragma unroll
        for (int r = 0; r < 4; r++) { A[r] = B[r]; B[r] = C[r]; }
    }

    // fold packed lanes, then warp reduce
    float S[4], T0[4], T1[4], T2[4];
#pragma unroll
    for (int r = 0; r < 4; r++) {
        float lo, hi;
        unpack2(lo, hi, Sp[r]);  S[r]  = lo + hi;
        unpack2(lo, hi, T0p[r]); T0[r] = lo + hi;
        unpack2(lo, hi, T1p[r]); T1[r] = lo + hi;
        unpack2(lo, hi, T2p[r]); T2[r] = lo + hi;
    }
#pragma unroll
    for (int o = 16; o > 0; o >>= 1) {
#pragma unroll
        for (int r = 0; r < 4; r++) {
            S[r]  += __shfl_xor_sync(0xffffffffu, S[r],  o);
            T0[r] += __shfl_xor_sync(0xffffffffu, T0[r], o);
            T1[r] += __shfl_xor_sync(0xffffffffu, T1[r], o);
            T2[r] += __shfl_xor_sync(0xffffffffu, T2[r], o);
        }
    }
    if (lane < 4) {
        int r = lane;
        float inv = 1.f / S[r];
        float v0 = T0[r] * inv, v1 = T1[r] * inv, v2 = T2[r] * inv;
        v0 = v0 > 0.f ? v0 : expm1f(v0);
        v1 = v1 > 0.f ? v1 : expm1f(v1);
        v2 = v2 > 0.f ? v2 : expm1f(v2);
        float* xp = g_x + ((size_t)b * NE + (ibase + r)) * 3;
        xp[0] = v0; xp[1] = v1; xp[2] = v2;
    }
}

// ---------------------------------------------------------------------------
// Kernel 4a: partial FC. grid (100, 12). chunk = 1024 floats, 1 float4/thread.
// ---------------------------------------------------------------------------
__global__ void __launch_bounds__(256) k_fc1(const float* __restrict__ w)
{
    int k = blockIdx.x, c = blockIdx.y;
    int n = c * 1024 + threadIdx.x * 4;
    const float* wr = w + (size_t)k * (NE * 3);
    float4 wv = *(const float4*)(wr + n);
    float4 v0 = *(const float4*)(g_x + 0 * NE * 3 + n);
    float4 v1 = *(const float4*)(g_x + 1 * NE * 3 + n);
    float4 v2 = *(const float4*)(g_x + 2 * NE * 3 + n);
    float4 v3 = *(const float4*)(g_x + 3 * NE * 3 + n);
    float a0 = fmaf(wv.x, v0.x, fmaf(wv.y, v0.y, fmaf(wv.z, v0.z, wv.w * v0.w)));
    float a1 = fmaf(wv.x, v1.x, fmaf(wv.y, v1.y, fmaf(wv.z, v1.z, wv.w * v1.w)));
    float a2 = fmaf(wv.x, v2.x, fmaf(wv.y, v2.y, fmaf(wv.z, v2.z, wv.w * v2.w)));
    float a3 = fmaf(wv.x, v3.x, fmaf(wv.y, v3.y, fmaf(wv.z, v3.z, wv.w * v3.w)));
#pragma unroll
    for (int o = 16; o > 0; o >>= 1) {
        a0 += __shfl_xor_sync(0xffffffffu, a0, o);
        a1 += __shfl_xor_sync(0xffffffffu, a1, o);
        a2 += __shfl_xor_sync(0xffffffffu, a2, o);
        a3 += __shfl_xor_sync(0xffffffffu, a3, o);
    }
    __shared__ float sred[4][8];
    int wrp = threadIdx.x >> 5, lane = threadIdx.x & 31;
    if (lane == 0) {
        sred[0][wrp] = a0; sred[1][wrp] = a1;
        sred[2][wrp] = a2; sred[3][wrp] = a3;
    }
    __syncthreads();
    if (threadIdx.x < 4) {
        float s = 0.f;
#pragma unroll
        for (int ww = 0; ww < 8; ww++) s += sred[threadIdx.x][ww];
        g_part[(c * 4 + threadIdx.x) * FCO + k] = s;
    }
}

// Kernel 4b: reduce partials + bias
__global__ void k_fc2(const float* __restrict__ bias, float* __restrict__ out)
{
    int tid = threadIdx.x;
    if (tid >= NB * FCO) return;
    int b = tid / FCO, k = tid % FCO;
    float s = __ldg(bias + k);
#pragma unroll
    for (int c = 0; c < NCHUNK; c++) s += g_part[(c * 4 + b) * FCO + k];
    out[b * FCO + k] = s;
}

// ---------------------------------------------------------------------------
extern "C" void kernel_launch(void* const* d_in, const int* in_sizes, int n_in,
                              void* d_out, int out_size)
{
    const int*   adj = (const int*)d_in[0];
    const float* emb = (const float*)d_in[1];
    const float* W   = (const float*)d_in[2];
    const float* av  = (const float*)d_in[3];
    const float* fcw = (const float*)d_in[4];
    const float* fcb = (const float*)d_in[5];
    float* out = (float*)d_out;

    cudaFuncSetAttribute(k_main, cudaFuncAttributeMaxDynamicSharedMemorySize,
                         5 * NE * (int)sizeof(float));

    k_init<<<1, 1>>>();
    k_prep<<<NE / 128, 128>>>(emb, W, av);
    k_tables<<<NE / 256, 256>>>();
    k_main<<<512, 256, 5 * NE * sizeof(float)>>>(adj);
    k_fc1<<<dim3(FCO, NCHUNK), 256>>>(fcw);
    k_fc2<<<1, 512>>>(fcb, out);
}

// round 4
// speedup vs baseline: 1.2572x; 1.0711x over previous
#include <cuda_runtime.h>
#include <math.h>

#define NE   4096
#define EMB  64
#define NB   4
#define FCO  100
#define NCHUNK 12
#define GRID 148
#define NITEM 1024          // NB * 128 row-tiles * 2 j-halves
#define STAGE_INTS 8192     // 32 rows x 256 j
#define NSTAGE 4
#define TBL_FLOATS (5 * NE)               // q,q2,h0,h1,h2
#define SMEM_BYTES (TBL_FLOATS * 4 + NSTAGE * STAGE_INTS * 4)   // 208KB

// Scratch (allocation-free rule: __device__ globals)
__device__ float g_h0[NE], g_h1[NE], g_h2[NE];
__device__ float g_src[NE], g_dst[NE];
__device__ float g_q[NE], g_q2[NE], g_ca[NE], g_cb[NE], g_w0[NE];
__device__ float g_x[NB * NE * 3];
__device__ float g_part[NCHUNK * NB * FCO];
__device__ float g_pS[2][NB * NE];
__device__ float g_pT0[2][NB * NE], g_pT1[2][NB * NE], g_pT2[2][NB * NE];
__device__ unsigned g_mbits;

__device__ __forceinline__ unsigned enc_f(float f) {
    unsigned b = __float_as_uint(f);
    return (b & 0x80000000u) ? ~b : (b | 0x80000000u);
}
__device__ __forceinline__ float dec_f(unsigned u) {
    unsigned b = (u & 0x80000000u) ? (u & 0x7fffffffu) : ~u;
    return __uint_as_float(b);
}
__device__ __forceinline__ unsigned smem_u32(const void* p) {
    return (unsigned)__cvta_generic_to_shared(p);
}
__device__ __forceinline__ void cp16(unsigned dst, const void* src) {
    asm volatile("cp.async.cg.shared.global [%0], [%1], 16;" :: "r"(dst), "l"(src) : "memory");
}
__device__ __forceinline__ void cp_commit() {
    asm volatile("cp.async.commit_group;" ::: "memory");
}
__device__ __forceinline__ void cp_wait3() {
    asm volatile("cp.async.wait_group 3;" ::: "memory");
}
__device__ __forceinline__ void cp_wait0() {
    asm volatile("cp.async.wait_group 0;" ::: "memory");
}

// ---------------------------------------------------------------------------
__global__ void k_init() { g_mbits = 0u; }

__global__ void k_prep(const float* __restrict__ emb,
                       const float* __restrict__ W,
                       const float* __restrict__ av)
{
    int row = blockIdx.x * blockDim.x + threadIdx.x;
    if (row >= NE) return;
    const float* e = emb + row * EMB;
    float h0 = 0.f, h1 = 0.f, h2 = 0.f;
#pragma unroll
    for (int k = 0; k < EMB; k++) {
        float ev = __ldg(e + k);
        h0 = fmaf(ev, __ldg(W + k * 3 + 0), h0);
        h1 = fmaf(ev, __ldg(W + k * 3 + 1), h1);
        h2 = fmaf(ev, __ldg(W + k * 3 + 2), h2);
    }
    g_h0[row] = h0; g_h1[row] = h1; g_h2[row] = h2;
    float s = h0 * __ldg(av + 0) + h1 * __ldg(av + 1) + h2 * __ldg(av + 2);
    float d = h0 * __ldg(av + 3) + h1 * __ldg(av + 4) + h2 * __ldg(av + 5);
    g_src[row] = s;
    g_dst[row] = d;
    atomicMax(&g_mbits, enc_f(d));
}

__global__ void k_tables()
{
    int i = blockIdx.x * blockDim.x + threadIdx.x;
    if (i >= NE) return;
    float Md = dec_f(g_mbits);
    float d = g_dst[i], s = g_src[i];
    g_q[i]  = expf(d - Md);
    g_q2[i] = expf(0.2f * (d - Md));
    float z  = s + Md;
    float lr = z > 0.f ? z : 0.2f * z;
    float C  = fmaxf(lr, 9e-15f);
    g_ca[i] = expf(z - C);
    g_cb[i] = expf(0.2f * z - C);
    g_w0[i] = expf(9e-15f - C);
}

// ---------------------------------------------------------------------------
// Kernel 3: persistent, cp.async 4-stage pipeline.
// Item = (b, 32-row tile, j-half of 2048). 8 stages/item, 256 j each.
// ---------------------------------------------------------------------------
__global__ void __launch_bounds__(256, 1) k_main(const int* __restrict__ adj)
{
    extern __shared__ float sm[];
    float* sq  = sm;
    float* sq2 = sm + NE;
    float* sh0 = sm + 2 * NE;
    float* sh1 = sm + 3 * NE;
    float* sh2 = sm + 4 * NE;
    int*   stg = (int*)(sm + TBL_FLOATS);

    int tid = threadIdx.x;
    int bid = blockIdx.x;
    int warp = tid >> 5, lane = tid & 31;

    // load tables (L2-resident broadcast)
    for (int i = tid; i < NE; i += 256) {
        sq[i] = g_q[i]; sq2[i] = g_q2[i];
        sh0[i] = g_h0[i]; sh1[i] = g_h1[i]; sh2[i] = g_h2[i];
    }

    int nItems = 0;
    for (int it = bid; it < NITEM; it += GRID) nItems++;
    int total = nItems * 8;

    // per-thread cp.async source layout: row_local = tid>>3, colgrp = tid&7
    int row_local = tid >> 3, colg = tid & 7;
    unsigned sdst_base = smem_u32(stg) + (unsigned)(row_local * 256 + colg * 4) * 4u;

    // issue one stage
    auto issue = [&](int gs) {
        int kIt = gs >> 3;
        int it = bid + kIt * GRID;
        int chunk = gs & 7, slot = gs & 3;
        int b = it >> 8, r32 = (it >> 1) & 127, jh = it & 1;
        const int* src = adj
            + (((size_t)((b << 12) + (r32 << 5) + row_local)) << 12)
            + (jh << 11) + (chunk << 8) + (colg << 2);
        unsigned dst = sdst_base + (unsigned)slot * (STAGE_INTS * 4u);
#pragma unroll
        for (int o = 0; o < 8; o++)
            cp16(dst + o * 128u, src + o * 32);
        cp_commit();
    };

    // prologue
    for (int gpre = 0; gpre < 3 && gpre < total; gpre++) issue(gpre);

    float S[4]  = {0, 0, 0, 0}, T0[4] = {0, 0, 0, 0};
    float T1[4] = {0, 0, 0, 0}, T2[4] = {0, 0, 0, 0};
    float Ca[4], Cb[4], W0[4];

    for (int g = 0; g < total; g++) {
        int kIt = g >> 3;
        int it = bid + kIt * GRID;
        int chunk = g & 7, slot = g & 3;
        int b = it >> 8, r32 = (it >> 1) & 127, jh = it & 1;
        int ibase = (r32 << 5) + (warp << 2);

        if (chunk == 0) {
#pragma unroll
            for (int r = 0; r < 4; r++) {
                Ca[r] = __ldg(&g_ca[ibase + r]);
                Cb[r] = __ldg(&g_cb[ibase + r]);
                W0[r] = __ldg(&g_w0[ibase + r]);
            }
        }

        if (g + 3 < total) { issue(g + 3); cp_wait3(); }
        else               { cp_wait0(); }
        __syncthreads();

        const int* st = stg + slot * STAGE_INTS + (warp << 2) * 256;
        int jbase = (jh << 11) + (chunk << 8);

#pragma unroll
        for (int g2 = 0; g2 < 2; g2++) {
            int jl = (g2 << 7) + (lane << 2);
            int jg = jbase + jl;
            float4 Q  = *(const float4*)(sq  + jg);
            float4 Q2 = *(const float4*)(sq2 + jg);
            float4 H0 = *(const float4*)(sh0 + jg);
            float4 H1 = *(const float4*)(sh1 + jg);
            float4 H2 = *(const float4*)(sh2 + jg);
#pragma unroll
            for (int r = 0; r < 4; r++) {
                int4 aa = *(const int4*)(st + r * 256 + jl);
                float m0 = fmaxf(Ca[r] * Q.x, Cb[r] * Q2.x);
                float m1 = fmaxf(Ca[r] * Q.y, Cb[r] * Q2.y);
                float m2 = fmaxf(Ca[r] * Q.z, Cb[r] * Q2.z);
                float m3 = fmaxf(Ca[r] * Q.w, Cb[r] * Q2.w);
                float w0 = (aa.x > 0) ? m0 : W0[r];
                float w1 = (aa.y > 0) ? m1 : W0[r];
                float w2 = (aa.z > 0) ? m2 : W0[r];
                float w3 = (aa.w > 0) ? m3 : W0[r];
                S[r]  += (w0 + w1) + (w2 + w3);
                T0[r] = fmaf(w0, H0.x, fmaf(w1, H0.y, fmaf(w2, H0.z, fmaf(w3, H0.w, T0[r]))));
                T1[r] = fmaf(w0, H1.x, fmaf(w1, H1.y, fmaf(w2, H1.z, fmaf(w3, H1.w, T1[r]))));
                T2[r] = fmaf(w0, H2.x, fmaf(w1, H2.y, fmaf(w2, H2.z, fmaf(w3, H2.w, T2[r]))));
            }
        }

        if (chunk == 7) {
            // reduce across lanes, write partials, reset
#pragma unroll
            for (int o = 16; o > 0; o >>= 1) {
#pragma unroll
                for (int r = 0; r < 4; r++) {
                    S[r]  += __shfl_xor_sync(0xffffffffu, S[r],  o);
                    T0[r] += __shfl_xor_sync(0xffffffffu, T0[r], o);
                    T1[r] += __shfl_xor_sync(0xffffffffu, T1[r], o);
                    T2[r] += __shfl_xor_sync(0xffffffffu, T2[r], o);
                }
            }
            if (lane == 0) {
                int rowg = (b << 12) + ibase;
#pragma unroll
                for (int r = 0; r < 4; r++) {
                    g_pS[jh][rowg + r]  = S[r];
                    g_pT0[jh][rowg + r] = T0[r];
                    g_pT1[jh][rowg + r] = T1[r];
                    g_pT2[jh][rowg + r] = T2[r];
                }
            }
#pragma unroll
            for (int r = 0; r < 4; r++) { S[r] = 0.f; T0[r] = 0.f; T1[r] = 0.f; T2[r] = 0.f; }
        }
        __syncthreads();
    }
}

// ---------------------------------------------------------------------------
// Kernel 3b: combine halves, normalize, ELU
__global__ void k_elu()
{
    int t = blockIdx.x * blockDim.x + threadIdx.x;
    if (t >= NB * NE) return;
    float S = g_pS[0][t] + g_pS[1][t];
    float inv = 1.f / S;
    float v0 = (g_pT0[0][t] + g_pT0[1][t]) * inv;
    float v1 = (g_pT1[0][t] + g_pT1[1][t]) * inv;
    float v2 = (g_pT2[0][t] + g_pT2[1][t]) * inv;
    v0 = v0 > 0.f ? v0 : expm1f(v0);
    v1 = v1 > 0.f ? v1 : expm1f(v1);
    v2 = v2 > 0.f ? v2 : expm1f(v2);
    g_x[t * 3 + 0] = v0;
    g_x[t * 3 + 1] = v1;
    g_x[t * 3 + 2] = v2;
}

// ---------------------------------------------------------------------------
// Kernel 4a: partial FC. grid (100, 12). chunk = 1024 floats, 1 float4/thread.
__global__ void __launch_bounds__(256) k_fc1(const float* __restrict__ w)
{
    int k = blockIdx.x, c = blockIdx.y;
    int n = c * 1024 + threadIdx.x * 4;
    const float* wr = w + (size_t)k * (NE * 3);
    float4 wv = *(const float4*)(wr + n);
    float4 v0 = *(const float4*)(g_x + 0 * NE * 3 + n);
    float4 v1 = *(const float4*)(g_x + 1 * NE * 3 + n);
    float4 v2 = *(const float4*)(g_x + 2 * NE * 3 + n);
    float4 v3 = *(const float4*)(g_x + 3 * NE * 3 + n);
    float a0 = fmaf(wv.x, v0.x, fmaf(wv.y, v0.y, fmaf(wv.z, v0.z, wv.w * v0.w)));
    float a1 = fmaf(wv.x, v1.x, fmaf(wv.y, v1.y, fmaf(wv.z, v1.z, wv.w * v1.w)));
    float a2 = fmaf(wv.x, v2.x, fmaf(wv.y, v2.y, fmaf(wv.z, v2.z, wv.w * v2.w)));
    float a3 = fmaf(wv.x, v3.x, fmaf(wv.y, v3.y, fmaf(wv.z, v3.z, wv.w * v3.w)));
#pragma unroll
    for (int o = 16; o > 0; o >>= 1) {
        a0 += __shfl_xor_sync(0xffffffffu, a0, o);
        a1 += __shfl_xor_sync(0xffffffffu, a1, o);
        a2 += __shfl_xor_sync(0xffffffffu, a2, o);
        a3 += __shfl_xor_sync(0xffffffffu, a3, o);
    }
    __shared__ float sred[4][8];
    int wrp = threadIdx.x >> 5, lane = threadIdx.x & 31;
    if (lane == 0) {
        sred[0][wrp] = a0; sred[1][wrp] = a1;
        sred[2][wrp] = a2; sred[3][wrp] = a3;
    }
    __syncthreads();
    if (threadIdx.x < 4) {
        float s = 0.f;
#pragma unroll
        for (int ww = 0; ww < 8; ww++) s += sred[threadIdx.x][ww];
        g_part[(c * 4 + threadIdx.x) * FCO + k] = s;
    }
}

__global__ void k_fc2(const float* __restrict__ bias, float* __restrict__ out)
{
    int tid = threadIdx.x;
    if (tid >= NB * FCO) return;
    int b = tid / FCO, k = tid % FCO;
    float s = __ldg(bias + k);
#pragma unroll
    for (int c = 0; c < NCHUNK; c++) s += g_part[(c * 4 + b) * FCO + k];
    out[b * FCO + k] = s;
}

// ---------------------------------------------------------------------------
extern "C" void kernel_launch(void* const* d_in, const int* in_sizes, int n_in,
                              void* d_out, int out_size)
{
    const int*   adj = (const int*)d_in[0];
    const float* emb = (const float*)d_in[1];
    const float* W   = (const float*)d_in[2];
    const float* av  = (const float*)d_in[3];
    const float* fcw = (const float*)d_in[4];
    const float* fcb = (const float*)d_in[5];
    float* out = (float*)d_out;

    cudaFuncSetAttribute(k_main, cudaFuncAttributeMaxDynamicSharedMemorySize,
                         SMEM_BYTES);

    k_init<<<1, 1>>>();
    k_prep<<<NE / 128, 128>>>(emb, W, av);
    k_tables<<<NE / 256, 256>>>();
    k_main<<<GRID, 256, SMEM_BYTES>>>(adj);
    k_elu<<<NB * NE / 256, 256>>>();
    k_fc1<<<dim3(FCO, NCHUNK), 256>>>(fcw);
    k_fc2<<<1, 512>>>(fcb, out);
}

// round 5
// speedup vs baseline: 1.3664x; 1.0868x over previous
#include <cuda_runtime.h>
#include <math.h>

#define NE   4096
#define EMB  64
#define NB   4
#define FCO  100
#define NCHUNK 12
#define GRID 148
#define NTHR 512
#define NWARP 16
#define NITEM 1024          // NB * 64 row-tiles * 4 j-quarters
#define TBL_FLOATS (5 * NE)                       // q,q2,h0,h1,h2 = 80KB
#define RING_INTS (NWARP * 4 * 512)               // 16 warps x 4 slots x 2KB = 128KB
#define SMEM_BYTES (TBL_FLOATS * 4 + RING_INTS * 4)   // 208KB

// Scratch (allocation-free rule: __device__ globals)
__device__ float g_h0[NE], g_h1[NE], g_h2[NE];
__device__ float g_src[NE], g_dst[NE];
__device__ float g_x[NB * NE * 3];
__device__ float g_part[NCHUNK * NB * FCO];
__device__ float g_pS[4][NB * NE];
__device__ float g_pT0[4][NB * NE], g_pT1[4][NB * NE], g_pT2[4][NB * NE];
__device__ unsigned g_mbits = 0u;   // static init; atomicMax idempotent across replays

__device__ __forceinline__ unsigned enc_f(float f) {
    unsigned b = __float_as_uint(f);
    return (b & 0x80000000u) ? ~b : (b | 0x80000000u);
}
__device__ __forceinline__ float dec_f(unsigned u) {
    unsigned b = (u & 0x80000000u) ? (u & 0x7fffffffu) : ~u;
    return __uint_as_float(b);
}
__device__ __forceinline__ unsigned smem_u32(const void* p) {
    return (unsigned)__cvta_generic_to_shared(p);
}
__device__ __forceinline__ void cp16(unsigned dst, const void* src) {
    asm volatile("cp.async.cg.shared.global [%0], [%1], 16;" :: "r"(dst), "l"(src) : "memory");
}
__device__ __forceinline__ void cp_commit() {
    asm volatile("cp.async.commit_group;" ::: "memory");
}
__device__ __forceinline__ void cp_wait3() {
    asm volatile("cp.async.wait_group 3;" ::: "memory");
}
__device__ __forceinline__ void cp_wait0() {
    asm volatile("cp.async.wait_group 0;" ::: "memory");
}

// ---------------------------------------------------------------------------
// Kernel 1: h = emb @ W, src/dst projections, global max(dst) via atomicMax
__global__ void k_prep(const float* __restrict__ emb,
                       const float* __restrict__ W,
                       const float* __restrict__ av)
{
    int row = blockIdx.x * blockDim.x + threadIdx.x;
    if (row >= NE) return;
    const float* e = emb + row * EMB;
    float h0 = 0.f, h1 = 0.f, h2 = 0.f;
#pragma unroll
    for (int k = 0; k < EMB; k++) {
        float ev = __ldg(e + k);
        h0 = fmaf(ev, __ldg(W + k * 3 + 0), h0);
        h1 = fmaf(ev, __ldg(W + k * 3 + 1), h1);
        h2 = fmaf(ev, __ldg(W + k * 3 + 2), h2);
    }
    g_h0[row] = h0; g_h1[row] = h1; g_h2[row] = h2;
    g_src[row] = h0 * __ldg(av + 0) + h1 * __ldg(av + 1) + h2 * __ldg(av + 2);
    float d    = h0 * __ldg(av + 3) + h1 * __ldg(av + 4) + h2 * __ldg(av + 5);
    g_dst[row] = d;
    atomicMax(&g_mbits, enc_f(d));
}

// ---------------------------------------------------------------------------
// Kernel 2: persistent. Per-WARP private cp.async ring (no CTA barriers in loop).
// Item = (b, 64-row tile, j-quarter of 1024). 8 steps/item, 128 j each.
// Warp w owns rows tile*64 + w*4 .. +3 for the item.
// ---------------------------------------------------------------------------
__global__ void __launch_bounds__(NTHR, 1) k_main(const int* __restrict__ adj)
{
    extern __shared__ float sm[];
    float* sq  = sm;
    float* sq2 = sm + NE;
    float* sh0 = sm + 2 * NE;
    float* sh1 = sm + 3 * NE;
    float* sh2 = sm + 4 * NE;
    int*   ring = (int*)(sm + TBL_FLOATS);

    int tid = threadIdx.x, bid = blockIdx.x;
    int warp = tid >> 5, lane = tid & 31;

    // Preamble: per-CTA table build (q, q2, h copies)
    float Md = dec_f(g_mbits);
    for (int i = tid; i < NE; i += NTHR) {
        float d = g_dst[i];
        sq[i]  = expf(d - Md);
        sq2[i] = expf(0.2f * (d - Md));
        sh0[i] = g_h0[i]; sh1[i] = g_h1[i]; sh2[i] = g_h2[i];
    }
    __syncthreads();   // only barrier

    int nItems = 0;
    for (int it = bid; it < NITEM; it += GRID) nItems++;
    int total = nItems * 8;

    int* wring = ring + warp * 2048;                 // 4 slots x 512 ints
    unsigned ring_base = smem_u32(wring);

    auto issue = [&](int step) {
        int kIt = step >> 3;
        int it  = bid + kIt * GRID;
        int chunk = step & 7, slot = step & 3;
        int b = it >> 8, tile = (it >> 2) & 63, jq = it & 3;
        const int* src = adj
            + ((size_t)((b << 12) + (tile << 6) + (warp << 2))) * NE
            + (jq << 10) + (chunk << 7) + (lane << 2);
        unsigned dst = ring_base + (unsigned)slot * 2048u + (unsigned)(lane << 4);
#pragma unroll
        for (int r = 0; r < 4; r++)
            cp16(dst + (unsigned)r * 512u, src + (size_t)r * NE);
        cp_commit();
    };

    for (int p = 0; p < 3 && p < total; p++) issue(p);

    float S[4]  = {0, 0, 0, 0}, T0[4] = {0, 0, 0, 0};
    float T1[4] = {0, 0, 0, 0}, T2[4] = {0, 0, 0, 0};
    float Ca[4], Cb[4], W0[4];

    for (int step = 0; step < total; step++) {
        int kIt = step >> 3;
        int it  = bid + kIt * GRID;
        int chunk = step & 7, slot = step & 3;
        int b = it >> 8, tile = (it >> 2) & 63, jq = it & 3;
        int row0 = (tile << 6) + (warp << 2);

        if (chunk == 0) {
#pragma unroll
            for (int r = 0; r < 4; r++) {
                float z  = __ldg(&g_src[row0 + r]) + Md;
                float lr = z > 0.f ? z : 0.2f * z;
                float C  = fmaxf(lr, 9e-15f);
                Ca[r] = expf(z - C);
                Cb[r] = expf(0.2f * z - C);
                W0[r] = expf(9e-15f - C);
            }
        }

        if (step + 3 < total) issue(step + 3);
        if (step + 3 < total) cp_wait3(); else cp_wait0();
        __syncwarp();

        const int* st = wring + slot * 512;
        int jg = (jq << 10) + (chunk << 7) + (lane << 2);
        float4 Q  = *(const float4*)(sq  + jg);
        float4 Q2 = *(const float4*)(sq2 + jg);
        float4 H0 = *(const float4*)(sh0 + jg);
        float4 H1 = *(const float4*)(sh1 + jg);
        float4 H2 = *(const float4*)(sh2 + jg);

#pragma unroll
        for (int r = 0; r < 4; r++) {
            int4 aa = *(const int4*)(st + (r << 7) + (lane << 2));
            float m0 = fmaxf(Ca[r] * Q.x, Cb[r] * Q2.x);
            float m1 = fmaxf(Ca[r] * Q.y, Cb[r] * Q2.y);
            float m2 = fmaxf(Ca[r] * Q.z, Cb[r] * Q2.z);
            float m3 = fmaxf(Ca[r] * Q.w, Cb[r] * Q2.w);
            float w0 = (aa.x > 0) ? m0 : W0[r];
            float w1 = (aa.y > 0) ? m1 : W0[r];
            float w2 = (aa.z > 0) ? m2 : W0[r];
            float w3 = (aa.w > 0) ? m3 : W0[r];
            S[r]  += (w0 + w1) + (w2 + w3);
            T0[r] = fmaf(w0, H0.x, fmaf(w1, H0.y, fmaf(w2, H0.z, fmaf(w3, H0.w, T0[r]))));
            T1[r] = fmaf(w0, H1.x, fmaf(w1, H1.y, fmaf(w2, H1.z, fmaf(w3, H1.w, T1[r]))));
            T2[r] = fmaf(w0, H2.x, fmaf(w1, H2.y, fmaf(w2, H2.z, fmaf(w3, H2.w, T2[r]))));
        }

        if (chunk == 7) {
#pragma unroll
            for (int o = 16; o > 0; o >>= 1) {
#pragma unroll
                for (int r = 0; r < 4; r++) {
                    S[r]  += __shfl_xor_sync(0xffffffffu, S[r],  o);
                    T0[r] += __shfl_xor_sync(0xffffffffu, T0[r], o);
                    T1[r] += __shfl_xor_sync(0xffffffffu, T1[r], o);
                    T2[r] += __shfl_xor_sync(0xffffffffu, T2[r], o);
                }
            }
            if (lane < 4) {
                int r = lane;
                int idx = (b << 12) + row0 + r;
                g_pS[jq][idx]  = S[r];
                g_pT0[jq][idx] = T0[r];
                g_pT1[jq][idx] = T1[r];
                g_pT2[jq][idx] = T2[r];
            }
#pragma unroll
            for (int r = 0; r < 4; r++) { S[r] = 0.f; T0[r] = 0.f; T1[r] = 0.f; T2[r] = 0.f; }
        }
    }
}

// ---------------------------------------------------------------------------
// Kernel 3: combine quarters, normalize, ELU
__global__ void k_elu()
{
    int t = blockIdx.x * blockDim.x + threadIdx.x;
    if (t >= NB * NE) return;
    float S  = (g_pS[0][t] + g_pS[1][t]) + (g_pS[2][t] + g_pS[3][t]);
    float inv = 1.f / S;
    float v0 = ((g_pT0[0][t] + g_pT0[1][t]) + (g_pT0[2][t] + g_pT0[3][t])) * inv;
    float v1 = ((g_pT1[0][t] + g_pT1[1][t]) + (g_pT1[2][t] + g_pT1[3][t])) * inv;
    float v2 = ((g_pT2[0][t] + g_pT2[1][t]) + (g_pT2[2][t] + g_pT2[3][t])) * inv;
    v0 = v0 > 0.f ? v0 : expm1f(v0);
    v1 = v1 > 0.f ? v1 : expm1f(v1);
    v2 = v2 > 0.f ? v2 : expm1f(v2);
    g_x[t * 3 + 0] = v0;
    g_x[t * 3 + 1] = v1;
    g_x[t * 3 + 2] = v2;
}

// ---------------------------------------------------------------------------
// Kernel 4a: partial FC. grid (100, 12). chunk = 1024 floats, 1 float4/thread.
__global__ void __launch_bounds__(256) k_fc1(const float* __restrict__ w)
{
    int k = blockIdx.x, c = blockIdx.y;
    int n = c * 1024 + threadIdx.x * 4;
    const float* wr = w + (size_t)k * (NE * 3);
    float4 wv = *(const float4*)(wr + n);
    float4 v0 = *(const float4*)(g_x + 0 * NE * 3 + n);
    float4 v1 = *(const float4*)(g_x + 1 * NE * 3 + n);
    float4 v2 = *(const float4*)(g_x + 2 * NE * 3 + n);
    float4 v3 = *(const float4*)(g_x + 3 * NE * 3 + n);
    float a0 = fmaf(wv.x, v0.x, fmaf(wv.y, v0.y, fmaf(wv.z, v0.z, wv.w * v0.w)));
    float a1 = fmaf(wv.x, v1.x, fmaf(wv.y, v1.y, fmaf(wv.z, v1.z, wv.w * v1.w)));
    float a2 = fmaf(wv.x, v2.x, fmaf(wv.y, v2.y, fmaf(wv.z, v2.z, wv.w * v2.w)));
    float a3 = fmaf(wv.x, v3.x, fmaf(wv.y, v3.y, fmaf(wv.z, v3.z, wv.w * v3.w)));
#pragma unroll
    for (int o = 16; o > 0; o >>= 1) {
        a0 += __shfl_xor_sync(0xffffffffu, a0, o);
        a1 += __shfl_xor_sync(0xffffffffu, a1, o);
        a2 += __shfl_xor_sync(0xffffffffu, a2, o);
        a3 += __shfl_xor_sync(0xffffffffu, a3, o);
    }
    __shared__ float sred[4][8];
    int wrp = threadIdx.x >> 5, lane = threadIdx.x & 31;
    if (lane == 0) {
        sred[0][wrp] = a0; sred[1][wrp] = a1;
        sred[2][wrp] = a2; sred[3][wrp] = a3;
    }
    __syncthreads();
    if (threadIdx.x < 4) {
        float s = 0.f;
#pragma unroll
        for (int ww = 0; ww < 8; ww++) s += sred[threadIdx.x][ww];
        g_part[(c * 4 + threadIdx.x) * FCO + k] = s;
    }
}

__global__ void k_fc2(const float* __restrict__ bias, float* __restrict__ out)
{
    int tid = threadIdx.x;
    if (tid >= NB * FCO) return;
    int b = tid / FCO, k = tid % FCO;
    float s = __ldg(bias + k);
#pragma unroll
    for (int c = 0; c < NCHUNK; c++) s += g_part[(c * 4 + b) * FCO + k];
    out[b * FCO + k] = s;
}

// ---------------------------------------------------------------------------
extern "C" void kernel_launch(void* const* d_in, const int* in_sizes, int n_in,
                              void* d_out, int out_size)
{
    const int*   adj = (const int*)d_in[0];
    const float* emb = (const float*)d_in[1];
    const float* W   = (const float*)d_in[2];
    const float* av  = (const float*)d_in[3];
    const float* fcw = (const float*)d_in[4];
    const float* fcb = (const float*)d_in[5];
    float* out = (float*)d_out;

    cudaFuncSetAttribute(k_main, cudaFuncAttributeMaxDynamicSharedMemorySize,
                         SMEM_BYTES);

    k_prep<<<NE / 128, 128>>>(emb, W, av);
    k_main<<<GRID, NTHR, SMEM_BYTES>>>(adj);
    k_elu<<<NB * NE / 256, 256>>>();
    k_fc1<<<dim3(FCO, NCHUNK), 256>>>(fcw);
    k_fc2<<<1, 512>>>(fcb, out);
}